// round 8
// baseline (speedup 1.0000x reference)
#include <cuda_runtime.h>
#include <cuda_fp16.h>
#include <cstdint>

// ============================================================
// IMDCT as one GEMM (overlap-add folded into K), fp16 datapath.
//   out[b, j, k2] = sum_{kappa<512} A[j,kappa] * Btilde[kappa,k2]
//   A[j, kappa<256]  = spec[b, kappa, j]        (j <= 4095, else 0)
//   A[j, kappa>=256] = spec[b, kappa-256, j-1]  (j >= 1, else 0)
// R6: warp tile 64x64 (0.031 B/FLOP smem -> tensor-bound), CTA 128x256,
// fused single prep kernel. B pre-scaled by 2^10, epilogue x 2^-10.
// ============================================================

#define N_FREQ    256
#define T_FRAMES  4096
#define M_ROWS    4097
#define OUT_PER_B (M_ROWS * 256)

#define M_TILE    128
#define NUM_PAIRS 8

#define SROWA_B   112                        // A smem row stride (28 words -> conflict-free)
#define A_PANEL   (129 * SROWA_B)            // 14448
#define SROWB_B   560                        // B smem row stride (140 words -> conflict-free)
#define B_PANEL   (32 * SROWB_B)             // 17920
#define STAGE_BYTES (A_PANEL + 2 * B_PANEL)  // 50288 (16B multiple)
#define SMEM_BYTES  (2 * STAGE_BYTES)        // 100576

__device__ __half g_specHT[16 * T_FRAMES * N_FREQ]; // [b][t][f] fp16
__device__ __half g_BmatH[512 * 256];               // [kappa][k2] fp16, x1024

__device__ __forceinline__ uint32_t smem_u32(const void* p) {
    uint32_t a;
    asm("{ .reg .u64 t; cvta.to.shared.u64 t, %1; cvt.u32.u64 %0, t; }" : "=r"(a) : "l"(p));
    return a;
}

// ---------------- fused prep: transpose+convert spec, build Bmat ----------------
__global__ void prep_kernel(const float* __restrict__ spec,
                            const float* __restrict__ kern)
{
    const int tid = threadIdx.x;
    if (blockIdx.z == 16) {
        if (blockIdx.y != 0) return;
        int base = (blockIdx.x * 256 + tid) * 8;     // 64 blocks cover 131072
        #pragma unroll
        for (int e = 0; e < 8; e++) {
            int i = base + e;
            int kappa = i >> 8;
            int k2    = i & 255;
            int trow  = k2 + ((kappa < 256) ? 0 : 256);
            g_BmatH[i] = __float2half_rn(kern[trow * 256 + (kappa & 255)] * 8.0f);
        }
        return;
    }
    __shared__ float tile[64][65];
    const int b  = blockIdx.z;
    const int t0 = blockIdx.x * 64;
    const int f0 = blockIdx.y * 64;
    const int tx = tid & 15, ty = tid >> 4;
    const float* src = spec + ((size_t)b * N_FREQ + f0) * T_FRAMES + t0;
    #pragma unroll
    for (int fi = 0; fi < 4; fi++) {
        int f = ty + fi * 16;
        float4 v = *(const float4*)(src + (size_t)f * T_FRAMES + tx * 4);
        tile[f][tx * 4 + 0] = v.x;
        tile[f][tx * 4 + 1] = v.y;
        tile[f][tx * 4 + 2] = v.z;
        tile[f][tx * 4 + 3] = v.w;
    }
    __syncthreads();
    __half* dst = g_specHT + ((size_t)b * T_FRAMES + t0) * N_FREQ + f0;
    const int fx = tid & 31, tr = tid >> 5;
    #pragma unroll
    for (int ti = 0; ti < 8; ti++) {
        int t = tr + ti * 8;
        __half2 v = __floats2half2_rn(tile[fx * 2][t], tile[fx * 2 + 1][t]);
        ((__half2*)(dst + (size_t)t * N_FREQ))[fx] = v;
    }
}

// ---------------- stage loader ----------------
__device__ __forceinline__ void load_stage(int b, int t0, int pair,
                                           uint32_t stage_base, int tid)
{
    const int f0 = pair * 32;
    const __half* HT = g_specHT;
    const __half* BM = g_BmatH;

    // A: 129 rows (t = t0-1+r) x 32 halves (64B = 4x16B)
    for (int i = tid; i < 129 * 4; i += 256) {
        int r  = i >> 2;
        int qq = i & 3;
        int t  = t0 - 1 + r;
        int valid = (t >= 0) && (t < T_FRAMES);
        int tc = valid ? t : 0;
        const char* src = (const char*)(HT + ((size_t)b * T_FRAMES + tc) * N_FREQ + f0) + qq * 16;
        uint32_t dst = stage_base + (uint32_t)(r * SROWA_B + qq * 16);
        uint32_t sz = valid ? 16u : 0u;
        asm volatile("cp.async.cg.shared.global [%0], [%1], 16, %2;"
                     :: "r"(dst), "l"(src), "r"(sz));
    }

    // B: 2 halves x 32 kappa-rows x 256 halves (512B = 32x16B)
    for (int i = tid; i < 2048; i += 256) {
        int h = i >> 10;
        int r = (i >> 5) & 31;
        int q = i & 31;
        const char* src = (const char*)(BM + (size_t)(h * 256 + f0 + r) * 256) + q * 16;
        uint32_t dst = stage_base + (uint32_t)(A_PANEL + h * B_PANEL + r * SROWB_B + q * 16);
        asm volatile("cp.async.cg.shared.global [%0], [%1], 16;"
                     :: "r"(dst), "l"(src));
    }
}

#define CP_COMMIT() asm volatile("cp.async.commit_group;" ::: "memory")
#define CP_WAIT1()  asm volatile("cp.async.wait_group 1;" ::: "memory")

#define LDSM_X4(r0,r1,r2,r3,addr) \
    asm volatile("ldmatrix.sync.aligned.m8n8.x4.shared.b16 {%0,%1,%2,%3}, [%4];" \
        : "=r"(r0), "=r"(r1), "=r"(r2), "=r"(r3) : "r"(addr))

#define LDSM_X4_T(r0,r1,r2,r3,addr) \
    asm volatile("ldmatrix.sync.aligned.m8n8.x4.trans.shared.b16 {%0,%1,%2,%3}, [%4];" \
        : "=r"(r0), "=r"(r1), "=r"(r2), "=r"(r3) : "r"(addr))

// ---------------- main GEMM kernel: CTA 128x256, warp 64x64 ----------------
__global__ void __launch_bounds__(256)
imdct_gemm_kernel(float* __restrict__ out)
{
    extern __shared__ __align__(16) char smemc[];
    const uint32_t sb = smem_u32(smemc);

    const int tid = threadIdx.x;
    const int wid = tid >> 5;
    const int lid = tid & 31;
    const int wm  = wid & 1;          // 2 warps along M (64 rows)
    const int wn  = wid >> 1;         // 4 warps along N (64 cols)
    const int tg  = lid & 3;
    const int g   = lid >> 2;

    const int t0 = blockIdx.x * M_TILE;
    const int b  = blockIdx.y;

    const int ltile = lid >> 3;       // ldmatrix lane roles
    const int lsub  = lid & 7;
    const int a_row8 = (ltile & 1) ? 8 : 0;
    const int a_col8 = (ltile & 2) ? 8 : 0;

    float c[4][8][4];
    #pragma unroll
    for (int mi = 0; mi < 4; mi++)
        #pragma unroll
        for (int ni = 0; ni < 8; ni++)
            #pragma unroll
            for (int e = 0; e < 4; e++) c[mi][ni][e] = 0.0f;

    load_stage(b, t0, 0, sb + 0 * STAGE_BYTES, tid); CP_COMMIT();
    load_stage(b, t0, 1, sb + 1 * STAGE_BYTES, tid); CP_COMMIT();

    for (int p = 0; p < NUM_PAIRS; p++) {
        CP_WAIT1();
        __syncthreads();

        const int st = p & 1;
        const uint32_t aBase = sb + st * STAGE_BYTES;
        const uint32_t bBase = aBase + A_PANEL;

        #pragma unroll
        for (int half = 0; half < 2; half++) {
            // A row for m: t = t0+m-half -> smem row m+1-half
            const uint32_t aHalf = aBase + (uint32_t)((1 - half) * SROWA_B);
            const uint32_t bH    = bBase + (uint32_t)(half * B_PANEL);

            #pragma unroll
            for (int ks = 0; ks < 2; ks++) {
                uint32_t a[4][4];
                #pragma unroll
                for (int mi = 0; mi < 4; mi++) {
                    int row = wm * 64 + mi * 16 + a_row8 + lsub;
                    uint32_t addr = aHalf + (uint32_t)(row * SROWA_B
                                  + (ks * 16 + a_col8) * 2);
                    LDSM_X4(a[mi][0], a[mi][1], a[mi][2], a[mi][3], addr);
                }
                uint32_t bf[8][2];
                #pragma unroll
                for (int pp = 0; pp < 4; pp++) {
                    int krow = ks * 16 + a_row8 + lsub;
                    uint32_t addr = bH + (uint32_t)(krow * SROWB_B
                                  + (wn * 64 + pp * 16 + a_col8) * 2);
                    LDSM_X4_T(bf[2 * pp][0], bf[2 * pp][1],
                              bf[2 * pp + 1][0], bf[2 * pp + 1][1], addr);
                }
                #pragma unroll
                for (int mi = 0; mi < 4; mi++)
                    #pragma unroll
                    for (int ni = 0; ni < 8; ni++) {
                        asm volatile(
                            "mma.sync.aligned.m16n8k16.row.col.f32.f16.f16.f32 "
                            "{%0,%1,%2,%3}, {%4,%5,%6,%7}, {%8,%9}, {%0,%1,%2,%3};"
                            : "+f"(c[mi][ni][0]), "+f"(c[mi][ni][1]),
                              "+f"(c[mi][ni][2]), "+f"(c[mi][ni][3])
                            : "r"(a[mi][0]), "r"(a[mi][1]),
                              "r"(a[mi][2]), "r"(a[mi][3]),
                              "r"(bf[ni][0]), "r"(bf[ni][1]));
                    }
            }
        }
        __syncthreads();

        if (p + 2 < NUM_PAIRS) {
            load_stage(b, t0, p + 2, sb + st * STAGE_BYTES, tid);
            CP_COMMIT();
        }
    }

    // epilogue: scale by 2^-10 and store
    const float scale = 1.0f / 1024.0f;
    float* outb = out + (size_t)b * OUT_PER_B;
    #pragma unroll
    for (int mi = 0; mi < 4; mi++) {
        int j0 = t0 + wm * 64 + mi * 16 + g;
        #pragma unroll
        for (int ni = 0; ni < 8; ni++) {
            int col = wn * 64 + ni * 8 + tg * 2;
            if (j0 <= 4096) {
                float2 v = make_float2(c[mi][ni][0] * scale, c[mi][ni][1] * scale);
                *(float2*)(outb + (size_t)j0 * 256 + col) = v;
            }
            if (j0 + 8 <= 4096) {
                float2 v = make_float2(c[mi][ni][2] * scale, c[mi][ni][3] * scale);
                *(float2*)(outb + (size_t)(j0 + 8) * 256 + col) = v;
            }
        }
    }
}

// ---------------- host launch ----------------
extern "C" void kernel_launch(void* const* d_in, const int* in_sizes, int n_in,
                              void* d_out, int out_size)
{
    const float* spec = (const float*)d_in[0];   // [16,1,256,4096]
    const float* kern = (const float*)d_in[1];   // [512,256]
    float* out = (float*)d_out;

    prep_kernel<<<dim3(T_FRAMES / 64, N_FREQ / 64, 17), 256>>>(spec, kern);

    cudaFuncSetAttribute(imdct_gemm_kernel,
                         cudaFuncAttributeMaxDynamicSharedMemorySize, SMEM_BYTES);
    imdct_gemm_kernel<<<dim3(33, 16), 256, SMEM_BYTES>>>(out);
}

// round 10
// speedup vs baseline: 1.7153x; 1.7153x over previous
#include <cuda_runtime.h>
#include <cuda_fp16.h>
#include <cstdint>

// ============================================================
// IMDCT as one GEMM (overlap-add folded into K), fp16 datapath.
//   out[b, j, k2] = sum_{kappa<512} A[j,kappa] * Btilde[kappa,k2]
//   A[j, kappa<256]  = spec[b, kappa, j]        (j <= 4095, else 0)
//   A[j, kappa>=256] = spec[b, kappa-256, j-1]  (j >= 1, else 0)
// R7: back to the proven 64x32 warp tile / 2 CTAs/SM operating point
// (R6's 64x64 tile hit the register file: 166 regs -> 1 CTA/SM).
// New: 3-stage cp.async pipeline with ONE __syncthreads per iteration.
// B pre-scaled by 2^10 (exact), epilogue x 2^-10.
// ============================================================

#define N_FREQ    256
#define T_FRAMES  4096
#define M_ROWS    4097
#define OUT_PER_B (M_ROWS * 256)

#define M_TILE    128
#define N_TILE    128
#define NUM_PAIRS 8
#define STAGES    3

#define SROWA_B   112                        // A row stride: 28 words -> conflict-free ldmatrix
#define A_PANEL   (129 * SROWA_B)            // 14448 (rows t0-1 .. t0+127)
#define SROWB_B   272                        // B row stride: 68 words -> conflict-free trans
#define B_PANEL   (32 * SROWB_B)             // 8704
#define STAGE_BYTES 31872                    // A_PANEL + 2*B_PANEL rounded to 16B
#define SMEM_BYTES  (STAGES * STAGE_BYTES)   // 95616 (x2 CTAs = 191 KB < 227 KB)

__device__ __half g_specHT[16 * T_FRAMES * N_FREQ]; // [b][t][f] fp16
__device__ __half g_BmatH[512 * 256];               // [kappa][k2] fp16, x1024

__device__ __forceinline__ uint32_t smem_u32(const void* p) {
    uint32_t a;
    asm("{ .reg .u64 t; cvta.to.shared.u64 t, %1; cvt.u32.u64 %0, t; }" : "=r"(a) : "l"(p));
    return a;
}

// ---------------- fused prep: transpose+convert spec, build Bmat ----------------
__global__ void prep_kernel(const float* __restrict__ spec,
                            const float* __restrict__ kern)
{
    const int tid = threadIdx.x;
    if (blockIdx.z == 16) {
        if (blockIdx.y != 0) return;
        int base = (blockIdx.x * 256 + tid) * 8;     // 64 x-blocks cover 131072
        #pragma unroll
        for (int e = 0; e < 8; e++) {
            int i = base + e;
            int kappa = i >> 8;
            int k2    = i & 255;
            int trow  = k2 + ((kappa < 256) ? 0 : 256);
            g_BmatH[i] = __float2half_rn(kern[trow * 256 + (kappa & 255)] * 8.0f);
        }
        return;
    }
    __shared__ float tile[64][65];
    const int b  = blockIdx.z;
    const int t0 = blockIdx.x * 64;
    const int f0 = blockIdx.y * 64;
    const int tx = tid & 15, ty = tid >> 4;
    const float* src = spec + ((size_t)b * N_FREQ + f0) * T_FRAMES + t0;
    #pragma unroll
    for (int fi = 0; fi < 4; fi++) {
        int f = ty + fi * 16;
        float4 v = *(const float4*)(src + (size_t)f * T_FRAMES + tx * 4);
        tile[f][tx * 4 + 0] = v.x;
        tile[f][tx * 4 + 1] = v.y;
        tile[f][tx * 4 + 2] = v.z;
        tile[f][tx * 4 + 3] = v.w;
    }
    __syncthreads();
    __half* dst = g_specHT + ((size_t)b * T_FRAMES + t0) * N_FREQ + f0;
    const int fx = tid & 31, tr = tid >> 5;
    #pragma unroll
    for (int ti = 0; ti < 8; ti++) {
        int t = tr + ti * 8;
        __half2 v = __floats2half2_rn(tile[fx * 2][t], tile[fx * 2 + 1][t]);
        ((__half2*)(dst + (size_t)t * N_FREQ))[fx] = v;
    }
}

// ---------------- stage loader ----------------
__device__ __forceinline__ void load_stage(int b, int t0, int n0, int pair,
                                           uint32_t stage_base, int tid)
{
    const int f0 = pair * 32;
    const __half* HT = g_specHT;
    const __half* BM = g_BmatH;

    // A: 129 rows (t = t0-1+r) x 32 halves (64B = 4x16B per row)
    for (int i = tid; i < 129 * 4; i += 256) {
        int r  = i >> 2;
        int qq = i & 3;
        int t  = t0 - 1 + r;
        int valid = (t >= 0) && (t < T_FRAMES);
        int tc = valid ? t : 0;
        const char* src = (const char*)(HT + ((size_t)b * T_FRAMES + tc) * N_FREQ + f0) + qq * 16;
        uint32_t dst = stage_base + (uint32_t)(r * SROWA_B + qq * 16);
        uint32_t sz = valid ? 16u : 0u;
        asm volatile("cp.async.cg.shared.global [%0], [%1], 16, %2;"
                     :: "r"(dst), "l"(src), "r"(sz));
    }

    // B: 2 halves x 32 kappa-rows x 128 halves (256B = 16x16B per row)
    for (int i = tid; i < 1024; i += 256) {
        int h = i >> 9;
        int r = (i >> 4) & 31;
        int q = i & 15;
        const char* src = (const char*)(BM + (size_t)(h * 256 + f0 + r) * 256 + n0) + q * 16;
        uint32_t dst = stage_base + (uint32_t)(A_PANEL + h * B_PANEL + r * SROWB_B + q * 16);
        asm volatile("cp.async.cg.shared.global [%0], [%1], 16;"
                     :: "r"(dst), "l"(src));
    }
}

#define CP_COMMIT() asm volatile("cp.async.commit_group;" ::: "memory")
#define CP_WAIT1()  asm volatile("cp.async.wait_group 1;" ::: "memory")

#define LDSM_X4(r0,r1,r2,r3,addr) \
    asm volatile("ldmatrix.sync.aligned.m8n8.x4.shared.b16 {%0,%1,%2,%3}, [%4];" \
        : "=r"(r0), "=r"(r1), "=r"(r2), "=r"(r3) : "r"(addr))

#define LDSM_X4_T(r0,r1,r2,r3,addr) \
    asm volatile("ldmatrix.sync.aligned.m8n8.x4.trans.shared.b16 {%0,%1,%2,%3}, [%4];" \
        : "=r"(r0), "=r"(r1), "=r"(r2), "=r"(r3) : "r"(addr))

// ---------------- main GEMM kernel: CTA 128x128, warp 64x32 ----------------
__global__ void __launch_bounds__(256, 2)
imdct_gemm_kernel(float* __restrict__ out)
{
    extern __shared__ __align__(16) char smemc[];
    const uint32_t sb = smem_u32(smemc);

    const int tid = threadIdx.x;
    const int wid = tid >> 5;
    const int lid = tid & 31;
    const int wm  = wid & 1;          // 2 warps along M (64 rows)
    const int wn  = wid >> 1;         // 4 warps along N (32 cols)
    const int tg  = lid & 3;
    const int g   = lid >> 2;

    const int t0 = blockIdx.x * M_TILE;
    const int n0 = blockIdx.y * N_TILE;
    const int b  = blockIdx.z;

    const int ltile = lid >> 3;       // ldmatrix lane roles
    const int lsub  = lid & 7;
    const int a_row8 = (ltile & 1) ? 8 : 0;
    const int a_col8 = (ltile & 2) ? 8 : 0;

    float c[4][4][4];
    #pragma unroll
    for (int mi = 0; mi < 4; mi++)
        #pragma unroll
        for (int ni = 0; ni < 4; ni++)
            #pragma unroll
            for (int e = 0; e < 4; e++) c[mi][ni][e] = 0.0f;

    // prologue: prefetch pairs 0,1 into stages 0,1
    load_stage(b, t0, n0, 0, sb + 0 * STAGE_BYTES, tid); CP_COMMIT();
    load_stage(b, t0, n0, 1, sb + 1 * STAGE_BYTES, tid); CP_COMMIT();

    for (int p = 0; p < NUM_PAIRS; p++) {
        CP_WAIT1();                       // pair p resident
        __syncthreads();                  // single barrier per iteration

        // prefetch pair p+2 into stage (p+2)%3 == (p-1)%3 (fully consumed)
        if (p + 2 < NUM_PAIRS) {
            load_stage(b, t0, n0, p + 2,
                       sb + (uint32_t)(((p + 2) % STAGES) * STAGE_BYTES), tid);
        }
        CP_COMMIT();                      // commit even if empty (keeps group count in sync)

        const uint32_t aBase = sb + (uint32_t)((p % STAGES) * STAGE_BYTES);
        const uint32_t bBase = aBase + A_PANEL;

        #pragma unroll
        for (int half = 0; half < 2; half++) {
            // A row for m: t = t0+m-half -> smem row m+1-half
            const uint32_t aHalf = aBase + (uint32_t)((1 - half) * SROWA_B);
            const uint32_t bH    = bBase + (uint32_t)(half * B_PANEL);

            #pragma unroll
            for (int ks = 0; ks < 2; ks++) {
                uint32_t a[4][4];
                #pragma unroll
                for (int mi = 0; mi < 4; mi++) {
                    int row = wm * 64 + mi * 16 + a_row8 + lsub;
                    uint32_t addr = aHalf + (uint32_t)(row * SROWA_B
                                  + (ks * 16 + a_col8) * 2);
                    LDSM_X4(a[mi][0], a[mi][1], a[mi][2], a[mi][3], addr);
                }
                uint32_t bf[4][2];
                #pragma unroll
                for (int pp = 0; pp < 2; pp++) {
                    int krow = ks * 16 + a_row8 + lsub;
                    uint32_t addr = bH + (uint32_t)(krow * SROWB_B
                                  + (wn * 32 + pp * 16 + a_col8) * 2);
                    LDSM_X4_T(bf[2 * pp][0], bf[2 * pp][1],
                              bf[2 * pp + 1][0], bf[2 * pp + 1][1], addr);
                }
                #pragma unroll
                for (int mi = 0; mi < 4; mi++)
                    #pragma unroll
                    for (int ni = 0; ni < 4; ni++) {
                        asm volatile(
                            "mma.sync.aligned.m16n8k16.row.col.f32.f16.f16.f32 "
                            "{%0,%1,%2,%3}, {%4,%5,%6,%7}, {%8,%9}, {%0,%1,%2,%3};"
                            : "+f"(c[mi][ni][0]), "+f"(c[mi][ni][1]),
                              "+f"(c[mi][ni][2]), "+f"(c[mi][ni][3])
                            : "r"(a[mi][0]), "r"(a[mi][1]),
                              "r"(a[mi][2]), "r"(a[mi][3]),
                              "r"(bf[ni][0]), "r"(bf[ni][1]));
                    }
            }
        }
        // no trailing barrier: next iteration's load targets the stage this
        // iteration just consumed, gated by the next CP_WAIT1+syncthreads.
    }

    // epilogue: scale by 2^-10 and store
    const float scale = 1.0f / 1024.0f;
    float* outb = out + (size_t)b * OUT_PER_B;
    #pragma unroll
    for (int mi = 0; mi < 4; mi++) {
        int j0 = t0 + wm * 64 + mi * 16 + g;
        #pragma unroll
        for (int ni = 0; ni < 4; ni++) {
            int col = n0 + wn * 32 + ni * 8 + tg * 2;
            if (j0 <= 4096) {
                float2 v = make_float2(c[mi][ni][0] * scale, c[mi][ni][1] * scale);
                *(float2*)(outb + (size_t)j0 * 256 + col) = v;
            }
            if (j0 + 8 <= 4096) {
                float2 v = make_float2(c[mi][ni][2] * scale, c[mi][ni][3] * scale);
                *(float2*)(outb + (size_t)(j0 + 8) * 256 + col) = v;
            }
        }
    }
}

// ---------------- host launch ----------------
extern "C" void kernel_launch(void* const* d_in, const int* in_sizes, int n_in,
                              void* d_out, int out_size)
{
    const float* spec = (const float*)d_in[0];   // [16,1,256,4096]
    const float* kern = (const float*)d_in[1];   // [512,256]
    float* out = (float*)d_out;

    prep_kernel<<<dim3(T_FRAMES / 64, N_FREQ / 64, 17), 256>>>(spec, kern);

    cudaFuncSetAttribute(imdct_gemm_kernel,
                         cudaFuncAttributeMaxDynamicSharedMemorySize, SMEM_BYTES);
    imdct_gemm_kernel<<<dim3(33, 2, 16), 256, SMEM_BYTES>>>(out);
}